// round 10
// baseline (speedup 1.0000x reference)
#include <cuda_runtime.h>
#include <cuda_bf16.h>
#include <cuda_fp16.h>
#include <mma.h>
#include <math.h>
#include <stdint.h>

using namespace nvcuda;

#define BB     16
#define MTOT   256
#define DD     4096
#define HKK    8
#define STARTP 2048
#define TTOT   2064
#define NKV    1024
#define NTILE  33
#define PSTRIDE (NTILE*64)   // 2112
#define VSTRIDE 2112
#define NPART  8

// f32 scratch
__device__ float g_k[MTOT * NKV];
__device__ float g_part_o[NPART * 128 * 64 * 128];
__device__ float g_sl[NTILE * 128 * 64];

// bf16 hi/lo (precision-critical: q/k projection, S)
__device__ __nv_bfloat16 g_xh[MTOT * DD],  g_xl[MTOT * DD];
__device__ __nv_bfloat16 g_qh[128 * 64 * 128], g_ql[128 * 64 * 128];
__device__ __nv_bfloat16 g_wqh[DD * DD],   g_wql[DD * DD];
__device__ __nv_bfloat16 g_wkh[DD * NKV],  g_wkl[DD * NKV];

// fp16 (linear paths)
__device__ __half g_xh16[MTOT * DD], g_xl16[MTOT * DD];
__device__ __half g_wv16[DD * NKV];
__device__ __half g_wo16[DD * DD];
__device__ __half g_v16[128 * VSTRIDE * 128];     // [bhk][t][d], rows 2064..2111 zero
__device__ __half g_p16[128 * 64 * PSTRIDE];
__device__ __half g_zh[MTOT * DD], g_zl[MTOT * DD];

// ---------------------------------------------------------------------------
__device__ __forceinline__ void split2(float a0, float a1,
                                       __nv_bfloat162* h, __nv_bfloat162* l)
{
    __nv_bfloat162 hh = __floats2bfloat162_rn(a0, a1);
    *h = hh;
    *l = __floats2bfloat162_rn(a0 - __low2float(hh), a1 - __high2float(hh));
}

__device__ __forceinline__ void split_store4(float4 v, float s,
                                             __nv_bfloat16* hp, __nv_bfloat16* lp)
{
    __nv_bfloat162 h0, l0, h1, l1;
    split2(v.x * s, v.y * s, &h0, &l0);
    split2(v.z * s, v.w * s, &h1, &l1);
    *(__nv_bfloat162*)(hp)     = h0;
    *(__nv_bfloat162*)(hp + 2) = h1;
    *(__nv_bfloat162*)(lp)     = l0;
    *(__nv_bfloat162*)(lp + 2) = l1;
}

__device__ __forceinline__ void split2h(float a0, float a1, __half2* h, __half2* l)
{
    __half2 hh = __floats2half2_rn(a0, a1);
    float2 hf = __half22float2(hh);
    *h = hh;
    *l = __floats2half2_rn(a0 - hf.x, a1 - hf.y);
}

__device__ __forceinline__ void cp16(uint32_t dst_smem, const void* src) {
    asm volatile("cp.async.ca.shared.global [%0], [%1], 16;"
                 :: "r"(dst_smem), "l"(src) : "memory");
}
#define CP_COMMIT() asm volatile("cp.async.commit_group;" ::: "memory")
#define CP_WAIT1()  asm volatile("cp.async.wait_group 1;" ::: "memory")
#define CP_WAIT0()  asm volatile("cp.async.wait_group 0;" ::: "memory")

// ---------------------------------------------------------------------------
// Merged preconversion, 4 float4 per thread (MLP=4).
// Segments in 1024-float4 blocks:
//   x[0,256) -> bf16 h/l + fp16 h/l     wq[256,4352)  -> bf16 h/l
//   wk[4352,5376) -> bf16 h/l           wv[5376,6400) -> fp16 single
//   wo[6400,10496) -> fp16 single       cache_v[10496,18688) -> g_v16 fp16
//   vzero[18688,18784) -> zero-fill g_v16 rows 2064..2111
// ---------------------------------------------------------------------------
__global__ __launch_bounds__(256)
void split_all_kernel(const float* __restrict__ x,  const float* __restrict__ wq,
                      const float* __restrict__ wk, const float* __restrict__ wv,
                      const float* __restrict__ wo, const float* __restrict__ cv)
{
    const int blk = blockIdx.x;
    const int tid = threadIdx.x;

    if (blk >= 18688) {   // vzero: 96 blocks, each thread 4x uint4 of zeros
        const int i0 = blk - 18688;
#pragma unroll
        for (int j = 0; j < 4; j++) {
            const int u = i0 * 1024 + tid + 256 * j;   // < 98304
            const int bhk = u / 768, r = u % 768;
            __half* dst = g_v16 + ((size_t)bhk * VSTRIDE + 2064) * 128 + r * 8;
            *(uint4*)dst = make_uint4(0u, 0u, 0u, 0u);
        }
        return;
    }
    if (blk >= 10496) {   // cache_v -> g_v16 fp16
        const int i0 = blk - 10496;
#pragma unroll
        for (int j = 0; j < 4; j++) {
            const int f = i0 * 1024 + tid + 256 * j;     // float4 index
            const int bhk = f >> 16;                      // 65536 f4 per bhk
            const int r   = f & 65535;
            const int t   = r >> 5, d4 = r & 31;
            float4 v = ((const float4*)cv)[((size_t)bhk * 4096 + t) * 32 + d4];
            __half* dst = g_v16 + ((size_t)bhk * VSTRIDE + t) * 128 + d4 * 4;
            *(__half2*)(dst)     = __floats2half2_rn(v.x, v.y);
            *(__half2*)(dst + 2) = __floats2half2_rn(v.z, v.w);
        }
        return;
    }

    const float* in; int i0; int mode;   // 0: bf16 h/l  1: fp16 single  2: x (both)
    __nv_bfloat16 *h = nullptr, *l = nullptr; __half* o16 = nullptr;
    if (blk < 256)        { in = x;  i0 = blk;        mode = 2; h = g_xh;  l = g_xl; }
    else if (blk < 4352)  { in = wq; i0 = blk - 256;  mode = 0; h = g_wqh; l = g_wql; }
    else if (blk < 5376)  { in = wk; i0 = blk - 4352; mode = 0; h = g_wkh; l = g_wkl; }
    else if (blk < 6400)  { in = wv; i0 = blk - 5376; mode = 1; o16 = g_wv16; }
    else                  { in = wo; i0 = blk - 6400; mode = 1; o16 = g_wo16; }

#pragma unroll
    for (int j = 0; j < 4; j++) {
        const int i = i0 * 1024 + tid + 256 * j;
        float4 v = ((const float4*)in)[i];
        if (mode == 1) {
            ((__half2*)o16)[2 * i]     = __floats2half2_rn(v.x, v.y);
            ((__half2*)o16)[2 * i + 1] = __floats2half2_rn(v.z, v.w);
        } else {
            __nv_bfloat162 h0, l0, h1, l1;
            split2(v.x, v.y, &h0, &l0);
            split2(v.z, v.w, &h1, &l1);
            ((__nv_bfloat162*)h)[2 * i]     = h0;
            ((__nv_bfloat162*)h)[2 * i + 1] = h1;
            ((__nv_bfloat162*)l)[2 * i]     = l0;
            ((__nv_bfloat162*)l)[2 * i + 1] = l1;
            if (mode == 2) {
                __half2 p0, q0, p1, q1;
                split2h(v.x, v.y, &p0, &q0);
                split2h(v.z, v.w, &p1, &q1);
                ((__half2*)g_xh16)[2 * i]     = p0;
                ((__half2*)g_xh16)[2 * i + 1] = p1;
                ((__half2*)g_xl16)[2 * i]     = q0;
                ((__half2*)g_xl16)[2 * i + 1] = q1;
            }
        }
    }
}

// ---------------------------------------------------------------------------
// q/k projection GEMM (bf16x3, cp.async double-buffered). grid (4, 40).
// ---------------------------------------------------------------------------
#define GA_LD 72
#define GB_LD 136
#define GS_LD 136
#define OFF_AH 0
#define OFF_AL (OFF_AH + 64 * GA_LD * 2)
#define OFF_BH (OFF_AL + 64 * GA_LD * 2)
#define OFF_BL (OFF_BH + 64 * GB_LD * 2)
#define STAGE_BYTES (OFF_BL + 64 * GB_LD * 2)
#define GEMM_SMEM (2 * STAGE_BYTES)

__global__ __launch_bounds__(256)
void gemm_qk(const float* __restrict__ Kout,
             const float* __restrict__ fc, const float* __restrict__ fs)
{
    extern __shared__ char sm[];
    const uint32_t sb = (uint32_t)__cvta_generic_to_shared(sm);

    const int tid = threadIdx.x;
    const int m0  = blockIdx.x * 64;
    const int nt  = blockIdx.y;

    const __nv_bfloat16 *Wh, *Wl; int Nc, dest, n0;
    if (nt < 32) { Wh = g_wqh; Wl = g_wql; Nc = 4096; dest = 0; n0 = nt * 128; }
    else         { Wh = g_wkh; Wl = g_wkl; Nc = 1024; dest = 1; n0 = (nt - 32) * 128; }

    const int warp = tid >> 5;
    const int rowg = warp >> 2;
    const int colg = warp & 3;
    const int ar = tid >> 3, ac = (tid & 7) * 8;
    const int br = tid >> 4, bc = (tid & 15) * 8;

    wmma::fragment<wmma::accumulator, 16, 16, 16, float> acc[2][2];
#pragma unroll
    for (int i = 0; i < 2; i++)
#pragma unroll
        for (int j = 0; j < 2; j++) wmma::fill_fragment(acc[i][j], 0.f);

    auto issue_stage = [&](int s, int k0) {
        const uint32_t st = sb + s * STAGE_BYTES;
#pragma unroll
        for (int j = 0; j < 2; j++) {
            const int r = ar + 32 * j;
            const size_t so = (size_t)(m0 + r) * DD + k0 + ac;
            cp16(st + OFF_AH + r * (GA_LD * 2) + ac * 2, g_xh + so);
            cp16(st + OFF_AL + r * (GA_LD * 2) + ac * 2, g_xl + so);
        }
#pragma unroll
        for (int j = 0; j < 4; j++) {
            const int r = br + 16 * j;
            const size_t so = (size_t)(k0 + r) * Nc + n0 + bc;
            cp16(st + OFF_BH + r * (GB_LD * 2) + bc * 2, Wh + so);
            cp16(st + OFF_BL + r * (GB_LD * 2) + bc * 2, Wl + so);
        }
        CP_COMMIT();
    };

    issue_stage(0, 0);

    const int NIT = DD / 64;
    for (int it = 0; it < NIT; it++) {
        if (it + 1 < NIT) { issue_stage((it + 1) & 1, (it + 1) * 64); CP_WAIT1(); }
        else              { CP_WAIT0(); }
        __syncthreads();

        const char* stg = sm + (it & 1) * STAGE_BYTES;
        const __nv_bfloat16* AHs = (const __nv_bfloat16*)(stg + OFF_AH);
        const __nv_bfloat16* ALs = (const __nv_bfloat16*)(stg + OFF_AL);
        const __nv_bfloat16* BHs = (const __nv_bfloat16*)(stg + OFF_BH);
        const __nv_bfloat16* BLs = (const __nv_bfloat16*)(stg + OFF_BL);

#pragma unroll
        for (int kk = 0; kk < 4; kk++) {
            wmma::fragment<wmma::matrix_a, 16, 16, 16, __nv_bfloat16, wmma::row_major> ah[2], al[2];
#pragma unroll
            for (int i = 0; i < 2; i++) {
                wmma::load_matrix_sync(ah[i], AHs + (rowg * 32 + 16 * i) * GA_LD + kk * 16, GA_LD);
                wmma::load_matrix_sync(al[i], ALs + (rowg * 32 + 16 * i) * GA_LD + kk * 16, GA_LD);
            }
#pragma unroll
            for (int j = 0; j < 2; j++) {
                wmma::fragment<wmma::matrix_b, 16, 16, 16, __nv_bfloat16, wmma::row_major> bh, bl;
                wmma::load_matrix_sync(bh, BHs + (kk * 16) * GB_LD + colg * 32 + 16 * j, GB_LD);
                wmma::load_matrix_sync(bl, BLs + (kk * 16) * GB_LD + colg * 32 + 16 * j, GB_LD);
#pragma unroll
                for (int i = 0; i < 2; i++) {
                    wmma::mma_sync(acc[i][j], ah[i], bh, acc[i][j]);
                    wmma::mma_sync(acc[i][j], ah[i], bl, acc[i][j]);
                    wmma::mma_sync(acc[i][j], al[i], bh, acc[i][j]);
                }
            }
        }
        __syncthreads();
    }

    float* SO = (float*)sm;
#pragma unroll
    for (int i = 0; i < 2; i++)
#pragma unroll
        for (int j = 0; j < 2; j++)
            wmma::store_matrix_sync(SO + (rowg * 32 + 16 * i) * GS_LD + colg * 32 + 16 * j,
                                    acc[i][j], GS_LD, wmma::mem_row_major);
    __syncthreads();

    const int erow = tid >> 2;
    const int ec0  = (tid & 3) * 32;
    const int m    = m0 + erow;
    const int tok  = m & 15;
    const float* srow = SO + erow * GS_LD + ec0;

    if (dest == 0) {
        const int h   = n0 >> 7;
        const int hk  = h >> 2, rep = h & 3;
        const int b   = m >> 4, n = m & 15;
        const size_t qb = ((size_t)(b * 8 + hk) * 64 + rep * 16 + n) * 128 + ec0;
#pragma unroll
        for (int j = 0; j < 32; j += 2) {
            const int p = (ec0 + j) >> 1;
            const float co = __ldg(fc + tok * 64 + p), si = __ldg(fs + tok * 64 + p);
            const float a = srow[j], bb = srow[j + 1];
            const float r0 = a * co - bb * si;
            const float r1 = a * si + bb * co;
            __nv_bfloat162 hh, ll;
            split2(r0 * 0.08838834764831845f, r1 * 0.08838834764831845f, &hh, &ll);
            *(__nv_bfloat162*)(g_qh + qb + j) = hh;
            *(__nv_bfloat162*)(g_ql + qb + j) = ll;
        }
    } else {
        float* orow = (float*)Kout + (size_t)m * NKV + n0 + ec0;
#pragma unroll
        for (int j = 0; j < 32; j += 2) {
            const int p = ((n0 + ec0 + j) & 127) >> 1;
            const float co = __ldg(fc + tok * 64 + p), si = __ldg(fs + tok * 64 + p);
            const float a = srow[j], bb = srow[j + 1];
            orow[j]     = a * co - bb * si;
            orow[j + 1] = a * si + bb * co;
        }
    }
}

// ---------------------------------------------------------------------------
// v projection: g_v16[.., 2048+n, ..] = x(fp16 h/l) @ wv(fp16). grid (4, 8).
// ---------------------------------------------------------------------------
#define WAH 0
#define WAL (WAH + 64 * GA_LD * 2)
#define WB  (WAL + 64 * GA_LD * 2)
#define WSTAGE (WB + 64 * GB_LD * 2)
#define WO_SMEM (2 * WSTAGE)

__global__ __launch_bounds__(256)
void gemm_v_fp16()
{
    extern __shared__ char sm[];
    const uint32_t sb = (uint32_t)__cvta_generic_to_shared(sm);

    const int tid = threadIdx.x;
    const int m0  = blockIdx.x * 64;
    const int hk  = blockIdx.y;
    const int n0  = hk * 128;

    const int warp = tid >> 5;
    const int rowg = warp >> 2;
    const int colg = warp & 3;
    const int ar = tid >> 3, ac = (tid & 7) * 8;
    const int br = tid >> 4, bc = (tid & 15) * 8;

    wmma::fragment<wmma::accumulator, 16, 16, 16, float> acc[2][2];
#pragma unroll
    for (int i = 0; i < 2; i++)
#pragma unroll
        for (int j = 0; j < 2; j++) wmma::fill_fragment(acc[i][j], 0.f);

    auto issue_stage = [&](int s, int k0) {
        const uint32_t st = sb + s * WSTAGE;
#pragma unroll
        for (int j = 0; j < 2; j++) {
            const int r = ar + 32 * j;
            const size_t so = (size_t)(m0 + r) * DD + k0 + ac;
            cp16(st + WAH + r * (GA_LD * 2) + ac * 2, g_xh16 + so);
            cp16(st + WAL + r * (GA_LD * 2) + ac * 2, g_xl16 + so);
        }
#pragma unroll
        for (int j = 0; j < 4; j++) {
            const int r = br + 16 * j;
            const size_t so = (size_t)(k0 + r) * NKV + n0 + bc;
            cp16(st + WB + r * (GB_LD * 2) + bc * 2, g_wv16 + so);
        }
        CP_COMMIT();
    };

    issue_stage(0, 0);

    const int NIT = DD / 64;
    for (int it = 0; it < NIT; it++) {
        if (it + 1 < NIT) { issue_stage((it + 1) & 1, (it + 1) * 64); CP_WAIT1(); }
        else              { CP_WAIT0(); }
        __syncthreads();

        const char* stg = sm + (it & 1) * WSTAGE;
        const __half* AHs = (const __half*)(stg + WAH);
        const __half* ALs = (const __half*)(stg + WAL);
        const __half* Bs  = (const __half*)(stg + WB);

#pragma unroll
        for (int kk = 0; kk < 4; kk++) {
            wmma::fragment<wmma::matrix_a, 16, 16, 16, __half, wmma::row_major> ah[2], al[2];
#pragma unroll
            for (int i = 0; i < 2; i++) {
                wmma::load_matrix_sync(ah[i], AHs + (rowg * 32 + 16 * i) * GA_LD + kk * 16, GA_LD);
                wmma::load_matrix_sync(al[i], ALs + (rowg * 32 + 16 * i) * GA_LD + kk * 16, GA_LD);
            }
#pragma unroll
            for (int j = 0; j < 2; j++) {
                wmma::fragment<wmma::matrix_b, 16, 16, 16, __half, wmma::row_major> bf;
                wmma::load_matrix_sync(bf, Bs + (kk * 16) * GB_LD + colg * 32 + 16 * j, GB_LD);
#pragma unroll
                for (int i = 0; i < 2; i++) {
                    wmma::mma_sync(acc[i][j], ah[i], bf, acc[i][j]);
                    wmma::mma_sync(acc[i][j], al[i], bf, acc[i][j]);
                }
            }
        }
        __syncthreads();
    }

    float* SO = (float*)sm;
#pragma unroll
    for (int i = 0; i < 2; i++)
#pragma unroll
        for (int j = 0; j < 2; j++)
            wmma::store_matrix_sync(SO + (rowg * 32 + 16 * i) * GS_LD + colg * 32 + 16 * j,
                                    acc[i][j], GS_LD, wmma::mem_row_major);
    __syncthreads();

    const int erow = tid >> 2;
    const int ec0  = (tid & 3) * 32;
    const int m    = m0 + erow;
    const int b    = m >> 4, n = m & 15;
    const float* srow = SO + erow * GS_LD + ec0;
    __half* dst = g_v16 + ((size_t)(b * 8 + hk) * VSTRIDE + 2048 + n) * 128 + ec0;
#pragma unroll
    for (int j = 0; j < 32; j += 2)
        *(__half2*)(dst + j) = __floats2half2_rn(srow[j], srow[j + 1]);
}

// ---------------------------------------------------------------------------
// wo GEMM (unchanged): out = z(fp16 h/l) @ wo(fp16). grid (4, 32).
// ---------------------------------------------------------------------------
__global__ __launch_bounds__(256)
void gemm_wo_fp16(float* __restrict__ out)
{
    extern __shared__ char sm[];
    const uint32_t sb = (uint32_t)__cvta_generic_to_shared(sm);

    const int tid = threadIdx.x;
    const int m0  = blockIdx.x * 64;
    const int n0  = blockIdx.y * 128;

    const int warp = tid >> 5;
    const int rowg = warp >> 2;
    const int colg = warp & 3;
    const int ar = tid >> 3, ac = (tid & 7) * 8;
    const int br = tid >> 4, bc = (tid & 15) * 8;

    wmma::fragment<wmma::accumulator, 16, 16, 16, float> acc[2][2];
#pragma unroll
    for (int i = 0; i < 2; i++)
#pragma unroll
        for (int j = 0; j < 2; j++) wmma::fill_fragment(acc[i][j], 0.f);

    auto issue_stage = [&](int s, int k0) {
        const uint32_t st = sb + s * WSTAGE;
#pragma unroll
        for (int j = 0; j < 2; j++) {
            const int r = ar + 32 * j;
            const size_t so = (size_t)(m0 + r) * DD + k0 + ac;
            cp16(st + WAH + r * (GA_LD * 2) + ac * 2, g_zh + so);
            cp16(st + WAL + r * (GA_LD * 2) + ac * 2, g_zl + so);
        }
#pragma unroll
        for (int j = 0; j < 4; j++) {
            const int r = br + 16 * j;
            const size_t so = (size_t)(k0 + r) * DD + n0 + bc;
            cp16(st + WB + r * (GB_LD * 2) + bc * 2, g_wo16 + so);
        }
        CP_COMMIT();
    };

    issue_stage(0, 0);

    const int NIT = DD / 64;
    for (int it = 0; it < NIT; it++) {
        if (it + 1 < NIT) { issue_stage((it + 1) & 1, (it + 1) * 64); CP_WAIT1(); }
        else              { CP_WAIT0(); }
        __syncthreads();

        const char* stg = sm + (it & 1) * WSTAGE;
        const __half* AHs = (const __half*)(stg + WAH);
        const __half* ALs = (const __half*)(stg + WAL);
        const __half* Bs  = (const __half*)(stg + WB);

#pragma unroll
        for (int kk = 0; kk < 4; kk++) {
            wmma::fragment<wmma::matrix_a, 16, 16, 16, __half, wmma::row_major> ah[2], al[2];
#pragma unroll
            for (int i = 0; i < 2; i++) {
                wmma::load_matrix_sync(ah[i], AHs + (rowg * 32 + 16 * i) * GA_LD + kk * 16, GA_LD);
                wmma::load_matrix_sync(al[i], ALs + (rowg * 32 + 16 * i) * GA_LD + kk * 16, GA_LD);
            }
#pragma unroll
            for (int j = 0; j < 2; j++) {
                wmma::fragment<wmma::matrix_b, 16, 16, 16, __half, wmma::row_major> bf;
                wmma::load_matrix_sync(bf, Bs + (kk * 16) * GB_LD + colg * 32 + 16 * j, GB_LD);
#pragma unroll
                for (int i = 0; i < 2; i++) {
                    wmma::mma_sync(acc[i][j], ah[i], bf, acc[i][j]);
                    wmma::mma_sync(acc[i][j], al[i], bf, acc[i][j]);
                }
            }
        }
        __syncthreads();
    }

    float* SO = (float*)sm;
#pragma unroll
    for (int i = 0; i < 2; i++)
#pragma unroll
        for (int j = 0; j < 2; j++)
            wmma::store_matrix_sync(SO + (rowg * 32 + 16 * i) * GS_LD + colg * 32 + 16 * j,
                                    acc[i][j], GS_LD, wmma::mem_row_major);
    __syncthreads();

    const int erow = tid >> 2;
    const int ec0  = (tid & 3) * 32;
    float* orow = out + (size_t)(m0 + erow) * DD + n0 + ec0;
    const float* srow = SO + erow * GS_LD + ec0;
#pragma unroll
    for (int j = 0; j < 32; j += 4)
        *(float4*)(orow + j) = *(const float4*)(srow + j);
}

// ---------------------------------------------------------------------------
// Kernel A: S tiles -> exp+mask -> P (single fp16). 4 key-tiles per CTA.
// ---------------------------------------------------------------------------
#define KA_LD 136
#define SQH 0
#define SQL (SQH + 64 * KA_LD * 2)
#define SKH (SQL + 64 * KA_LD * 2)
#define SKL (SKH + 64 * KA_LD * 2)
#define SSS (SKL + 64 * KA_LD * 2)
#define KA_SMEM (SSS + 64 * 72 * 4)

__device__ __forceinline__ void load_k_regs(const float* __restrict__ cache,
                                            int b, int hk, int t0, int tid, float4* reg)
{
    const int tcnt = min(64, TTOT - t0);
#pragma unroll
    for (int i = 0; i < 8; i++) {
        const int idx = tid + 256 * i;
        const int tt = idx >> 5, c4 = (idx & 31) * 4;
        const int t = t0 + tt;
        float4 v = make_float4(0.f, 0.f, 0.f, 0.f);
        if (tt < tcnt) {
            v = (t < STARTP)
              ? *(const float4*)(cache + (((size_t)b * HKK + hk) * 4096 + t) * 128 + c4)
              : *(const float4*)(g_k + (size_t)(b * 16 + (t - STARTP)) * NKV + hk * 128 + c4);
        }
        reg[i] = v;
    }
}

__global__ __launch_bounds__(256)
void attn_s_kernel(const float* __restrict__ cache_k)
{
    extern __shared__ char sm[];
    const uint32_t sb = (uint32_t)__cvta_generic_to_shared(sm);
    __nv_bfloat16* QH = (__nv_bfloat16*)(sm + SQH);
    __nv_bfloat16* QL = (__nv_bfloat16*)(sm + SQL);
    __nv_bfloat16* KH = (__nv_bfloat16*)(sm + SKH);
    __nv_bfloat16* KL = (__nv_bfloat16*)(sm + SKL);
    float*         S  = (float*)(sm + SSS);

    const int grp  = blockIdx.x;
    const int bhk  = blockIdx.y;
    const int b    = bhk >> 3, hk = bhk & 7;
    const int tid  = threadIdx.x;
    const int warp = tid >> 5;

    const int tile_b = grp * 4;
    const int tile_e = min(tile_b + 4, NTILE);

    {
        const int r = tid >> 2, q4 = (tid & 3) * 32;
        const size_t gq = ((size_t)bhk * 64 + r) * 128 + q4;
#pragma unroll
        for (int jj = 0; jj < 4; jj++) {
            const int off = q4 + 8 * jj;
            cp16(sb + SQH + r * (KA_LD * 2) + off * 2, g_qh + gq + 8 * jj);
            cp16(sb + SQL + r * (KA_LD * 2) + off * 2, g_ql + gq + 8 * jj);
        }
        CP_COMMIT();
    }

    float4 kreg[8];
    load_k_regs(cache_k, b, hk, tile_b * 64, tid, kreg);
    CP_WAIT0();

    const int rq = warp >> 1;
    const int cw = warp & 1;

    for (int tile = tile_b; tile < tile_e; tile++) {
        const int t0 = tile * 64;
        const int tcnt = min(64, TTOT - t0);

#pragma unroll
        for (int i = 0; i < 8; i++) {
            const int idx = tid + 256 * i;
            const int tt = idx >> 5, c4 = (idx & 31) * 4;
            split_store4(kreg[i], 1.f, &KH[tt * KA_LD + c4], &KL[tt * KA_LD + c4]);
        }
        __syncthreads();

        if (tile + 1 < tile_e)
            load_k_regs(cache_k, b, hk, (tile + 1) * 64, tid, kreg);

        wmma::fragment<wmma::accumulator, 16, 16, 16, float> sacc[2];
        wmma::fill_fragment(sacc[0], 0.f);
        wmma::fill_fragment(sacc[1], 0.f);
#pragma unroll
        for (int kk = 0; kk < 8; kk++) {
            wmma::fragment<wmma::matrix_a, 16, 16, 16, __nv_bfloat16, wmma::row_major> qh, ql;
            wmma::load_matrix_sync(qh, QH + (rq * 16) * KA_LD + kk * 16, KA_LD);
            wmma::load_matrix_sync(ql, QL + (rq * 16) * KA_LD + kk * 16, KA_LD);
#pragma unroll
            for (int j = 0; j < 2; j++) {
                const int tc = cw * 32 + 16 * j;
                wmma::fragment<wmma::matrix_b, 16, 16, 16, __nv_bfloat16, wmma::col_major> khf, klf;
                wmma::load_matrix_sync(khf, KH + tc * KA_LD + kk * 16, KA_LD);
                wmma::load_matrix_sync(klf, KL + tc * KA_LD + kk * 16, KA_LD);
                wmma::mma_sync(sacc[j], qh, khf, sacc[j]);
                wmma::mma_sync(sacc[j], qh, klf, sacc[j]);
                wmma::mma_sync(sacc[j], ql, khf, sacc[j]);
            }
        }
        wmma::store_matrix_sync(S + (rq * 16) * 72 + cw * 32,      sacc[0], 72, wmma::mem_row_major);
        wmma::store_matrix_sync(S + (rq * 16) * 72 + cw * 32 + 16, sacc[1], 72, wmma::mem_row_major);
        __syncthreads();

        {
            const int srow = tid >> 2, sub = tid & 3;
            const int lim = STARTP + (srow & 15);
            const float* Srow = S + srow * 72 + sub * 16;
            const size_t pb = ((size_t)bhk * 64 + srow) * PSTRIDE + t0 + sub * 16;
            float ls = 0.f;
#pragma unroll
            for (int c = 0; c < 16; c += 2) {
                const int col = sub * 16 + c;
                const int t = t0 + col;
                float p0 = 0.f, p1 = 0.f;
                if (col < tcnt && t <= lim)         p0 = __expf(Srow[c]);
                if (col + 1 < tcnt && t + 1 <= lim) p1 = __expf(Srow[c + 1]);
                ls += p0 + p1;
                *(__half2*)(g_p16 + pb + c) = __floats2half2_rn(p0, p1);
            }
            ls += __shfl_xor_sync(0xffffffffu, ls, 1);
            ls += __shfl_xor_sync(0xffffffffu, ls, 2);
            if (sub == 0) g_sl[(size_t)tile * 8192 + bhk * 64 + srow] = ls;
        }
    }
}

// ---------------------------------------------------------------------------
// Kernel B: O_part = P(fp16) @ V(fp16), pure cp.async double-buffered.
// grid (NPART, 128). smem 53248 B -> 4 CTAs/SM.
// ---------------------------------------------------------------------------
#define PV_PLD 72
#define PV_PST (64 * PV_PLD * 2)        // 9216
#define PV_VLD 136
#define PV_VST (64 * PV_VLD * 2)        // 17408
#define PV_V0  (2 * PV_PST)             // 18432
#define PV_SMEM (PV_V0 + 2 * PV_VST)    // 53248

__global__ __launch_bounds__(256)
void attn_pv_kernel()
{
    extern __shared__ char sm[];
    const uint32_t sb = (uint32_t)__cvta_generic_to_shared(sm);

    const int part = blockIdx.x;
    const int bhk  = blockIdx.y;
    const int tid  = threadIdx.x;
    const int warp = tid >> 5;

    const int tb = (part == 0) ? 0 : 4 * part + 1;
    const int te = 4 * part + 5;

    const int rw = warp >> 1;
    const int ch = warp & 1;
    wmma::fragment<wmma::accumulator, 16, 16, 16, float> oacc[4];
#pragma unroll
    for (int ct = 0; ct < 4; ct++) wmma::fill_fragment(oacc[ct], 0.f);

    const int r  = tid >> 2;
    const int c2 = tid & 3;

    auto issue = [&](int t, int s) {
        // P tile: 64 x 64 fp16
        const __half* psrc = g_p16 + ((size_t)bhk * 64 + r) * PSTRIDE + t * 64 + c2 * 16;
        const uint32_t pst = sb + s * PV_PST + r * (PV_PLD * 2) + c2 * 32;
#pragma unroll
        for (int jj = 0; jj < 2; jj++)
            cp16(pst + jj * 16, psrc + jj * 8);
        // V tile: 64 x 128 fp16
        const __half* vsrc = g_v16 + ((size_t)bhk * VSTRIDE + t * 64 + r) * 128 + c2 * 32;
        const uint32_t vst = sb + PV_V0 + s * PV_VST + r * (PV_VLD * 2) + c2 * 64;
#pragma unroll
        for (int jj = 0; jj < 4; jj++)
            cp16(vst + jj * 16, vsrc + jj * 8);
        CP_COMMIT();
    };

    issue(tb, 0);

    for (int t = tb; t < te; t++) {
        const int s = (t - tb) & 1;
        if (t + 1 < te) { issue(t + 1, s ^ 1); CP_WAIT1(); }
        else            { CP_WAIT0(); }
        __syncthreads();

        const __half* PS = (const __half*)(sm + s * PV_PST);
        const __half* VS = (const __half*)(sm + PV_V0 + s * PV_VST);
#pragma unroll
        for (int kk = 0; kk < 4; kk++) {
            wmma::fragment<wmma::matrix_a, 16, 16, 16, __half, wmma::row_major> pa;
            wmma::load_matrix_sync(pa, PS + (rw * 16) * PV_PLD + kk * 16, PV_PLD);
#pragma unroll
            for (int ct = 0; ct < 4; ct++) {
                wmma::fragment<wmma::matrix_b, 16, 16, 16, __half, wmma::row_major> vf;
                wmma::load_matrix_sync(vf, VS + (kk * 16) * PV_VLD + ch * 64 + 16 * ct, PV_VLD);
                wmma::mma_sync(oacc[ct], pa, vf, oacc[ct]);
            }
        }
        __syncthreads();
    }

    const size_t pbase = (size_t)(part * 128 + bhk) * 64;
#pragma unroll
    for (int ct = 0; ct < 4; ct++)
        wmma::store_matrix_sync(g_part_o + (pbase + rw * 16) * 128 + ch * 64 + 16 * ct,
                                oacc[ct], 128, wmma::mem_row_major);
}

// ---------------------------------------------------------------------------
// Combine -> z (fp16 hi/lo)
// ---------------------------------------------------------------------------
__global__ __launch_bounds__(256)
void attn_combine_kernel()
{
    const int by  = blockIdx.x;
    const int b   = by >> 3, hk = by & 7;
    const int tid = threadIdx.x;
    const int row = tid >> 2;
    const int dq  = tid & 3;

    float lsum = 0.f;
    for (int t = 0; t < NTILE; t++)
        lsum += g_sl[(size_t)t * 8192 + by * 64 + row];
    const float inv = 1.f / lsum;

    const int rep = row >> 4, n = row & 15;
    const size_t obase = (size_t)(b * 16 + n) * DD + (hk * 4 + rep) * 128 + dq * 32;

#pragma unroll
    for (int d4 = 0; d4 < 8; d4++) {
        float4 acc = make_float4(0.f, 0.f, 0.f, 0.f);
#pragma unroll
        for (int g = 0; g < NPART; g++) {
            const float4 v = *(const float4*)(g_part_o +
                ((size_t)(g * 128 + by) * 64 + row) * 128 + dq * 32 + d4 * 4);
            acc.x += v.x; acc.y += v.y; acc.z += v.z; acc.w += v.w;
        }
        acc.x *= inv; acc.y *= inv; acc.z *= inv; acc.w *= inv;
        __half2 h0, l0, h1, l1;
        split2h(acc.x, acc.y, &h0, &l0);
        split2h(acc.z, acc.w, &h1, &l1);
        *(__half2*)(g_zh + obase + d4 * 4)     = h0;
        *(__half2*)(g_zh + obase + d4 * 4 + 2) = h1;
        *(__half2*)(g_zl + obase + d4 * 4)     = l0;
        *(__half2*)(g_zl + obase + d4 * 4 + 2) = l1;
    }
}

// ---------------------------------------------------------------------------
extern "C" void kernel_launch(void* const* d_in, const int* in_sizes, int n_in,
                              void* d_out, int out_size)
{
    (void)in_sizes; (void)n_in; (void)out_size;
    const float* x  = (const float*)d_in[0];
    const float* fc = (const float*)d_in[1];
    const float* fs = (const float*)d_in[2];
    const float* ck = (const float*)d_in[4];
    const float* cv = (const float*)d_in[5];
    const float* wq = (const float*)d_in[6];
    const float* wk = (const float*)d_in[7];
    const float* wv = (const float*)d_in[8];
    const float* wo = (const float*)d_in[9];
    float* out = (float*)d_out;

    float* pk;
    cudaGetSymbolAddress((void**)&pk, g_k);

    cudaFuncSetAttribute(gemm_qk,
                         cudaFuncAttributeMaxDynamicSharedMemorySize, GEMM_SMEM);
    cudaFuncSetAttribute(gemm_v_fp16,
                         cudaFuncAttributeMaxDynamicSharedMemorySize, WO_SMEM);
    cudaFuncSetAttribute(gemm_wo_fp16,
                         cudaFuncAttributeMaxDynamicSharedMemorySize, WO_SMEM);
    cudaFuncSetAttribute(attn_s_kernel,
                         cudaFuncAttributeMaxDynamicSharedMemorySize, KA_SMEM);
    cudaFuncSetAttribute(attn_pv_kernel,
                         cudaFuncAttributeMaxDynamicSharedMemorySize, PV_SMEM);

    // Preconversion (MLP=4), incl. cache_v -> fp16 + zero pad
    split_all_kernel<<<18784, 256>>>(x, wq, wk, wv, wo, cv);

    // Projections
    gemm_qk<<<dim3(4, 40), 256, GEMM_SMEM>>>(pk, fc, fs);
    gemm_v_fp16<<<dim3(4, 8), 256, WO_SMEM>>>();

    // Attention
    attn_s_kernel<<<dim3(9, 128), 256, KA_SMEM>>>(ck);
    attn_pv_kernel<<<dim3(NPART, 128), 256, PV_SMEM>>>();
    attn_combine_kernel<<<128, 256>>>();

    // Output projection
    gemm_wo_fp16<<<dim3(4, 32), 256, WO_SMEM>>>(out);
}